// round 10
// baseline (speedup 1.0000x reference)
#include <cuda_runtime.h>
#include <math.h>

#define NN 100000
#define DD 128
#define HH 64
#define CC 40
#define NB 391          // ceil(NN/256) scan blocks

typedef unsigned long long u64;

// ---- scratch (__device__ globals per harness rules) ----
__device__ float g_y1[(size_t)NN * HH];     // x @ W1l            25.6 MB
__device__ float g_self[(size_t)NN * HH];   // x @ W1r + b1       25.6 MB
__device__ float g_h[(size_t)NN * HH];      // layer-1 output     25.6 MB
__device__ float g_agg2[(size_t)NN * HH];   // mean(h[nbrs])      25.6 MB
__device__ int   g_cnt[NN];
__device__ int   g_rowptr[NN];
__device__ int   g_cur[NN];
__device__ float g_invdeg[NN];
__device__ int   g_srcs[2000000];
__device__ int   g_exc[NB * 256];
__device__ int   g_bsum[512];
__device__ int   g_is64;

// ---- f32x2 packed-math helpers (sm_103a FFMA2) ----
__device__ __forceinline__ u64 pack2(float lo, float hi) {
    u64 r;
    asm("mov.b64 %0, {%1, %2};" : "=l"(r) : "f"(lo), "f"(hi));
    return r;
}
__device__ __forceinline__ void unpack2(u64 v, float& lo, float& hi) {
    asm("mov.b64 {%0, %1}, %2;" : "=f"(lo), "=f"(hi) : "l"(v));
}
__device__ __forceinline__ void fma2(u64& d, u64 a, u64 b) {
    asm("fma.rn.f32x2 %0, %1, %2, %0;" : "+l"(d) : "l"(a), "l"(b));
}

// ---------------------------------------------------------------------------
__global__ void k_detzero(const void* __restrict__ ei) {
    int i = blockIdx.x * blockDim.x + threadIdx.x;
    if (i < NN) g_cnt[i] = 0;
    if (blockIdx.x == 0) {
        if (threadIdx.x == 0) g_is64 = 1;
        __syncthreads();
        if (threadIdx.x < 128) {
            long long v = ((const long long*)ei)[threadIdx.x];
            if (v < 0 || v >= NN) atomicAnd(&g_is64, 0);
        }
    }
}

__global__ void k_hist(const void* __restrict__ ei, int nE) {
    int e = blockIdx.x * blockDim.x + threadIdx.x;
    if (e >= nE) return;
    int d = g_is64 ? (int)((const long long*)ei)[nE + e]
                   : ((const int*)ei)[nE + e];
    atomicAdd(&g_cnt[d], 1);
}

__global__ void k_scan1() {
    __shared__ int sh[256];
    int t = threadIdx.x, b = blockIdx.x;
    int i = b * 256 + t;
    int v = (i < NN) ? g_cnt[i] : 0;
    sh[t] = v;
    __syncthreads();
    #pragma unroll
    for (int off = 1; off < 256; off <<= 1) {
        int u = (t >= off) ? sh[t - off] : 0;
        __syncthreads();
        sh[t] += u;
        __syncthreads();
    }
    if (i < NN) g_exc[i] = sh[t] - v;
    if (t == 255) g_bsum[b] = sh[t];
}

__global__ void k_scan23() {
    __shared__ int red[8];
    __shared__ int boff;
    int b = blockIdx.x, t = threadIdx.x;
    int v = 0;
    if (t < b) v = g_bsum[t];
    if (t + 256 < b) v += g_bsum[t + 256];
    #pragma unroll
    for (int o = 16; o; o >>= 1) v += __shfl_xor_sync(0xffffffffu, v, o);
    if ((t & 31) == 0) red[t >> 5] = v;
    __syncthreads();
    if (t == 0) {
        int s = 0;
        #pragma unroll
        for (int j = 0; j < 8; ++j) s += red[j];
        boff = s;
    }
    __syncthreads();
    int i = b * 256 + t;
    if (i < NN) {
        int row = g_exc[i] + boff;
        g_rowptr[i] = row;
        g_cur[i] = row;
        g_invdeg[i] = 1.0f / fmaxf((float)g_cnt[i], 1.0f);
    }
}

__global__ void k_fill(const void* __restrict__ ei, int nE) {
    int e = blockIdx.x * blockDim.x + threadIdx.x;
    if (e >= nE) return;
    int s, d;
    if (g_is64) {
        const long long* p = (const long long*)ei;
        s = (int)p[e]; d = (int)p[nE + e];
    } else {
        const int* p = (const int*)ei;
        s = p[e]; d = p[nE + e];
    }
    int pos = atomicAdd(&g_cur[d], 1);
    g_srcs[pos] = s;
}

// ---------------------------------------------------------------------------
// GEMM1 v4: [y1 | self+b1] = x[N,128] @ [W1l | W1r][128,128]
// 128x128 tile, 256 threads, 8x8 microtile, K-chunk 64 (only 2 phases).
// A in smem as packed row-pair u64: As2[k][mp] = (x[2mp][k], x[2mp+1][k]).
// B in smem duplicated (b,b) u64, pitch 129 to break STS bank conflicts.
// Inner loop per k: 4 LDS.64(A, broadcast) + 8 LDS.64(B) + 32 FFMA2.
// Dynamic smem ~99KB (2 blocks/SM).
// ---------------------------------------------------------------------------
#define G1_A_PITCH 65    // u64 pitch for As2 (64 pairs + 1 pad)
#define G1_B_PITCH 129   // u64 pitch for Bs2 (128 cols + 1 pad)
#define G1_SMEM (64 * G1_A_PITCH * 8 + 64 * G1_B_PITCH * 8)

__global__ void __launch_bounds__(256, 2)
k_gemm1(const float* __restrict__ x,
        const float* __restrict__ Wl,
        const float* __restrict__ Wr,
        const float* __restrict__ b) {
    extern __shared__ unsigned char smraw[];
    u64 (*As2)[G1_A_PITCH] = (u64(*)[G1_A_PITCH])smraw;                 // [k][mp]
    u64 (*Bs2)[G1_B_PITCH] = (u64(*)[G1_B_PITCH])(smraw + 64 * G1_A_PITCH * 8); // [k][n]

    int tid = threadIdx.x;
    int tx = tid & 15;        // col lane: cols {tx, tx+16, ..., tx+112}
    int ty = tid >> 4;        // row-pair group: pairs ty*4 .. ty*4+3
    int m0 = blockIdx.x * 128;

    u64 acc[4][8] = {};       // [rowpair i][col j]

    #pragma unroll 1
    for (int c = 0; c < 2; ++c) {
        int kb = c * 64;
        __syncthreads();
        // ---- load A: 64 row-pairs x 64 k. thread: pair rp, k-quarter q.
        {
            int rp = tid >> 2;           // 0..63
            int q  = tid & 3;            // 0..3 -> kk0 = q*16
            int r0 = min(m0 + 2 * rp, NN - 1);
            int r1 = min(m0 + 2 * rp + 1, NN - 1);
            const float* xr0 = x + (size_t)r0 * DD + kb + q * 16;
            const float* xr1 = x + (size_t)r1 * DD + kb + q * 16;
            #pragma unroll
            for (int i = 0; i < 4; ++i) {
                float4 a = __ldg((const float4*)(xr0 + i * 4));
                float4 bq = __ldg((const float4*)(xr1 + i * 4));
                int kk = q * 16 + i * 4;
                As2[kk + 0][rp] = pack2(a.x, bq.x);
                As2[kk + 1][rp] = pack2(a.y, bq.y);
                As2[kk + 2][rp] = pack2(a.z, bq.z);
                As2[kk + 3][rp] = pack2(a.w, bq.w);
            }
        }
        // ---- load B: 64 k-rows x 128 cols, duplicated. thread: row k, quarter.
        {
            int k = tid & 63;            // 0..63
            int half = tid >> 6;         // 0..3 -> cols half*32 .. +31
            int n0 = half * 32;
            const float* W = (n0 < 64) ? (Wl + (size_t)(kb + k) * 64 + n0)
                                       : (Wr + (size_t)(kb + k) * 64 + (n0 - 64));
            #pragma unroll
            for (int i = 0; i < 8; ++i) {
                float4 v = __ldg((const float4*)(W + i * 4));
                int n = n0 + i * 4;
                Bs2[k][n + 0] = pack2(v.x, v.x);
                Bs2[k][n + 1] = pack2(v.y, v.y);
                Bs2[k][n + 2] = pack2(v.z, v.z);
                Bs2[k][n + 3] = pack2(v.w, v.w);
            }
        }
        __syncthreads();
        // ---- compute: 64 k-steps
        #pragma unroll 4
        for (int k = 0; k < 64; ++k) {
            u64 Ap[4];
            #pragma unroll
            for (int i = 0; i < 4; ++i)
                Ap[i] = As2[k][ty * 4 + i];
            #pragma unroll
            for (int j = 0; j < 8; ++j) {
                u64 Bv = Bs2[k][j * 16 + tx];
                fma2(acc[0][j], Ap[0], Bv);
                fma2(acc[1][j], Ap[1], Bv);
                fma2(acc[2][j], Ap[2], Bv);
                fma2(acc[3][j], Ap[3], Bv);
            }
        }
    }

    // epilogue: col<64 -> g_y1 ; col>=64 -> g_self (+b1).
    #pragma unroll
    for (int j = 0; j < 8; ++j) {
        int col = j * 16 + tx;
        bool isSelf = (col >= 64);
        int nc = isSelf ? (col - 64) : col;
        float bb = isSelf ? b[nc] : 0.f;
        float* dst = isSelf ? g_self : g_y1;
        #pragma unroll
        for (int i = 0; i < 4; ++i) {
            float v0, v1;
            unpack2(acc[i][j], v0, v1);
            int r0 = m0 + (ty * 4 + i) * 2;
            if (r0 < NN)     dst[(size_t)r0 * HH + nc]       = v0 + bb;
            if (r0 + 1 < NN) dst[(size_t)(r0 + 1) * HH + nc] = v1 + bb;
        }
    }
}

// ---------------------------------------------------------------------------
// agg1 + ReLU: h[n] = relu( invdeg * sum_{s} y1[s] + self[n] )
// ---------------------------------------------------------------------------
__global__ void k_agg1(void) {
    int w = (blockIdx.x * blockDim.x + threadIdx.x) >> 5;
    int lane = threadIdx.x & 31;
    if (w >= NN) return;
    int beg = g_rowptr[w], n = g_cnt[w];
    const float2* yb = (const float2*)g_y1;
    float2 a0 = make_float2(0.f, 0.f), a1 = make_float2(0.f, 0.f);
    int e = 0;
    for (; e + 1 < n; e += 2) {
        int s0 = g_srcs[beg + e];
        int s1 = g_srcs[beg + e + 1];
        float2 v0 = __ldg(yb + (size_t)s0 * 32 + lane);
        float2 v1 = __ldg(yb + (size_t)s1 * 32 + lane);
        a0.x += v0.x; a0.y += v0.y;
        a1.x += v1.x; a1.y += v1.y;
    }
    if (e < n) {
        int s0 = g_srcs[beg + e];
        float2 v0 = __ldg(yb + (size_t)s0 * 32 + lane);
        a0.x += v0.x; a0.y += v0.y;
    }
    float sc = g_invdeg[w];
    float2 s = ((const float2*)g_self)[(size_t)w * 32 + lane];
    float2 o;
    o.x = fmaxf((a0.x + a1.x) * sc + s.x, 0.f);
    o.y = fmaxf((a0.y + a1.y) * sc + s.y, 0.f);
    ((float2*)g_h)[(size_t)w * 32 + lane] = o;
}

// ---------------------------------------------------------------------------
// agg2: g_agg2[n] = invdeg * sum_{s} h[s]
// ---------------------------------------------------------------------------
__global__ void k_agg2(void) {
    int w = (blockIdx.x * blockDim.x + threadIdx.x) >> 5;
    int lane = threadIdx.x & 31;
    if (w >= NN) return;
    int beg = g_rowptr[w], n = g_cnt[w];
    const float2* hb = (const float2*)g_h;
    float2 a0 = make_float2(0.f, 0.f), a1 = make_float2(0.f, 0.f);
    int e = 0;
    for (; e + 1 < n; e += 2) {
        int s0 = g_srcs[beg + e];
        int s1 = g_srcs[beg + e + 1];
        float2 v0 = __ldg(hb + (size_t)s0 * 32 + lane);
        float2 v1 = __ldg(hb + (size_t)s1 * 32 + lane);
        a0.x += v0.x; a0.y += v0.y;
        a1.x += v1.x; a1.y += v1.y;
    }
    if (e < n) {
        int s0 = g_srcs[beg + e];
        float2 v0 = __ldg(hb + (size_t)s0 * 32 + lane);
        a0.x += v0.x; a0.y += v0.y;
    }
    float sc = g_invdeg[w];
    float2 o;
    o.x = (a0.x + a1.x) * sc;
    o.y = (a0.y + a1.y) * sc;
    ((float2*)g_agg2)[(size_t)w * 32 + lane] = o;
}

// ---------------------------------------------------------------------------
// GEMM2 + fused log_softmax (warp per node), packed f32x2. 1024 threads/block
// to amortize the weight smem fill (4x fewer blocks -> 4x less L2 traffic).
// ---------------------------------------------------------------------------
__global__ void k_gemm2(const float* __restrict__ Wl,
                        const float* __restrict__ Wr,
                        const float* __restrict__ b,
                        float* __restrict__ out) {
    __shared__ float2 sW[64 * 40];
    __shared__ float sb[40];
    int tid = threadIdx.x;
    for (int i = tid; i < 64 * 40; i += blockDim.x)
        sW[i] = make_float2(Wl[i], Wr[i]);
    if (tid < 40) sb[tid] = b[tid];
    __syncthreads();

    int w = (blockIdx.x * blockDim.x + tid) >> 5;
    int lane = tid & 31;
    if (w >= NN) return;
    bool lo8 = (lane < 8);

    const float* ag = g_agg2 + (size_t)w * HH;
    const float* hr = g_h    + (size_t)w * HH;
    float a0 = ag[lane], a1 = ag[lane + 32];
    float h0 = hr[lane], h1 = hr[lane + 32];

    u64 acc0 = 0, acc1 = 0;
    #pragma unroll
    for (int k = 0; k < 32; ++k) {
        float av = __shfl_sync(0xffffffffu, a0, k);
        float hv = __shfl_sync(0xffffffffu, h0, k);
        u64 p = pack2(av, hv);
        fma2(acc0, p, *(const u64*)&sW[k * 40 + lane]);
        if (lo8) fma2(acc1, p, *(const u64*)&sW[k * 40 + 32 + lane]);
    }
    #pragma unroll
    for (int k = 0; k < 32; ++k) {
        float av = __shfl_sync(0xffffffffu, a1, k);
        float hv = __shfl_sync(0xffffffffu, h1, k);
        u64 p = pack2(av, hv);
        int kr = k + 32;
        fma2(acc0, p, *(const u64*)&sW[kr * 40 + lane]);
        if (lo8) fma2(acc1, p, *(const u64*)&sW[kr * 40 + 32 + lane]);
    }

    float u0, v0, u1, v1;
    unpack2(acc0, u0, v0);
    unpack2(acc1, u1, v1);
    float z0 = u0 + v0 + sb[lane];
    float z1 = lo8 ? (u1 + v1 + sb[32 + lane]) : -INFINITY;

    float m = fmaxf(z0, z1);
    #pragma unroll
    for (int o = 16; o; o >>= 1) m = fmaxf(m, __shfl_xor_sync(0xffffffffu, m, o));
    float e = expf(z0 - m) + (lo8 ? expf(z1 - m) : 0.f);
    #pragma unroll
    for (int o = 16; o; o >>= 1) e += __shfl_xor_sync(0xffffffffu, e, o);
    float lse = logf(e) + m;

    out[(size_t)w * CC + lane] = z0 - lse;
    if (lo8) out[(size_t)w * CC + 32 + lane] = z1 - lse;
}

// ---------------------------------------------------------------------------
extern "C" void kernel_launch(void* const* d_in, const int* in_sizes, int n_in,
                              void* d_out, int out_size) {
    const float* x   = (const float*)d_in[0];
    const void*  ei  = d_in[1];
    const float* W1l = (const float*)d_in[2];
    const float* W1r = (const float*)d_in[3];
    const float* b1  = (const float*)d_in[4];
    const float* W2l = (const float*)d_in[5];
    const float* W2r = (const float*)d_in[6];
    const float* b2  = (const float*)d_in[7];
    float* out = (float*)d_out;

    int nE = in_sizes[1] / 2;
    int eBlocks = (nE + 255) / 256;
    int nWarpBlocks = (NN * 32 + 255) / 256;

    // allow ~99KB dynamic smem for gemm1 (idempotent; host-side, capture-safe)
    cudaFuncSetAttribute(k_gemm1, cudaFuncAttributeMaxDynamicSharedMemorySize,
                         G1_SMEM);

    k_detzero<<<(NN + 255) / 256, 256>>>(ei);            // 1
    k_hist<<<eBlocks, 256>>>(ei, nE);                    // 2
    k_scan1<<<NB, 256>>>();                              // 3
    k_gemm1<<<(NN + 127) / 128, 256, G1_SMEM>>>(x, W1l, W1r, b1); // 4 <- ncu
    k_scan23<<<NB, 256>>>();                             // 5
    k_fill<<<eBlocks, 256>>>(ei, nE);                    // 6
    k_agg1<<<nWarpBlocks, 256>>>();                      // 7
    k_agg2<<<nWarpBlocks, 256>>>();                      // 8
    k_gemm2<<<(NN + 31) / 32, 1024>>>(W2l, W2r, b2, out); // 9
}

// round 11
// speedup vs baseline: 1.0176x; 1.0176x over previous
#include <cuda_runtime.h>
#include <math.h>

#define NN 100000
#define DD 128
#define HH 64
#define CC 40
#define NB 391          // ceil(NN/256) scan blocks

typedef unsigned long long u64;

// ---- scratch (__device__ globals per harness rules) ----
__device__ float g_y1[(size_t)NN * HH];     // x @ W1l            25.6 MB
__device__ float g_self[(size_t)NN * HH];   // x @ W1r + b1       25.6 MB
__device__ float g_h[(size_t)NN * HH];      // layer-1 output     25.6 MB
__device__ float g_agg2[(size_t)NN * HH];   // mean(h[nbrs])      25.6 MB
__device__ int   g_cnt[NN];
__device__ int   g_rowptr[NN];
__device__ int   g_cur[NN];
__device__ float g_invdeg[NN];
__device__ int   g_srcs[2000000];
__device__ int   g_exc[NB * 256];
__device__ int   g_bsum[512];
__device__ int   g_is64;

// ---- f32x2 packed-math helpers (sm_103a FFMA2) ----
__device__ __forceinline__ u64 pack2(float lo, float hi) {
    u64 r;
    asm("mov.b64 %0, {%1, %2};" : "=l"(r) : "f"(lo), "f"(hi));
    return r;
}
__device__ __forceinline__ void unpack2(u64 v, float& lo, float& hi) {
    asm("mov.b64 {%0, %1}, %2;" : "=f"(lo), "=f"(hi) : "l"(v));
}
__device__ __forceinline__ void fma2(u64& d, u64 a, u64 b) {
    asm("fma.rn.f32x2 %0, %1, %2, %0;" : "+l"(d) : "l"(a), "l"(b));
}

// ---------------------------------------------------------------------------
__global__ void k_detzero(const void* __restrict__ ei) {
    int i = blockIdx.x * blockDim.x + threadIdx.x;
    if (i < NN) g_cnt[i] = 0;
    if (blockIdx.x == 0) {
        if (threadIdx.x == 0) g_is64 = 1;
        __syncthreads();
        if (threadIdx.x < 128) {
            long long v = ((const long long*)ei)[threadIdx.x];
            if (v < 0 || v >= NN) atomicAnd(&g_is64, 0);
        }
    }
}

__global__ void k_hist(const void* __restrict__ ei, int nE) {
    int e = blockIdx.x * blockDim.x + threadIdx.x;
    if (e >= nE) return;
    int d = g_is64 ? (int)((const long long*)ei)[nE + e]
                   : ((const int*)ei)[nE + e];
    atomicAdd(&g_cnt[d], 1);
}

__global__ void k_scan1() {
    __shared__ int sh[256];
    int t = threadIdx.x, b = blockIdx.x;
    int i = b * 256 + t;
    int v = (i < NN) ? g_cnt[i] : 0;
    sh[t] = v;
    __syncthreads();
    #pragma unroll
    for (int off = 1; off < 256; off <<= 1) {
        int u = (t >= off) ? sh[t - off] : 0;
        __syncthreads();
        sh[t] += u;
        __syncthreads();
    }
    if (i < NN) g_exc[i] = sh[t] - v;
    if (t == 255) g_bsum[b] = sh[t];
}

__global__ void k_scan23() {
    __shared__ int red[8];
    __shared__ int boff;
    int b = blockIdx.x, t = threadIdx.x;
    int v = 0;
    if (t < b) v = g_bsum[t];
    if (t + 256 < b) v += g_bsum[t + 256];
    #pragma unroll
    for (int o = 16; o; o >>= 1) v += __shfl_xor_sync(0xffffffffu, v, o);
    if ((t & 31) == 0) red[t >> 5] = v;
    __syncthreads();
    if (t == 0) {
        int s = 0;
        #pragma unroll
        for (int j = 0; j < 8; ++j) s += red[j];
        boff = s;
    }
    __syncthreads();
    int i = b * 256 + t;
    if (i < NN) {
        int row = g_exc[i] + boff;
        g_rowptr[i] = row;
        g_cur[i] = row;
        g_invdeg[i] = 1.0f / fmaxf((float)g_cnt[i], 1.0f);
    }
}

__global__ void k_fill(const void* __restrict__ ei, int nE) {
    int e = blockIdx.x * blockDim.x + threadIdx.x;
    if (e >= nE) return;
    int s, d;
    if (g_is64) {
        const long long* p = (const long long*)ei;
        s = (int)p[e]; d = (int)p[nE + e];
    } else {
        const int* p = (const int*)ei;
        s = p[e]; d = p[nE + e];
    }
    int pos = atomicAdd(&g_cur[d], 1);
    g_srcs[pos] = s;
}

// ---------------------------------------------------------------------------
// GEMM1 (r9 measured version): [y1 | self+b1] = x[N,128] @ [W1l|W1r][128,128]
// 128x128 tile, 256 threads, 8x8 microtile, K-chunk 16, static smem.
// ---------------------------------------------------------------------------
__global__ void __launch_bounds__(256, 2)
k_gemm1(const float* __restrict__ x,
        const float* __restrict__ Wl,
        const float* __restrict__ Wr,
        const float* __restrict__ b) {
    __shared__ float As[16][130];     // [k][m], pitch 130: 8B-aligned u64 reads
    __shared__ u64   Bs2[16][128];    // duplicated (b,b) pairs

    int tid = threadIdx.x;
    int tx = tid & 15;        // col lane: cols {tx, tx+16, ..., tx+112}
    int ty = tid >> 4;        // row group: rows ty*8 .. ty*8+7
    int m0 = blockIdx.x * 128;

    u64 acc[4][8] = {};       // [rowpair][col j]

    #pragma unroll 1
    for (int c = 0; c < 8; ++c) {
        int kb = c * 16;
        __syncthreads();
        {
            int m  = tid >> 2;             // 0..63
            int kk = (tid & 3) * 4;        // 0,4,8,12
            #pragma unroll
            for (int r = 0; r < 2; ++r, m += 64) {
                int mg = min(m0 + m, NN - 1);
                float4 v = __ldg((const float4*)(x + (size_t)mg * DD + kb + kk));
                As[kk + 0][m] = v.x;
                As[kk + 1][m] = v.y;
                As[kk + 2][m] = v.z;
                As[kk + 3][m] = v.w;
            }
        }
        {
            int k = tid >> 4;              // 0..15
            int n = (tid & 15) * 8;        // 0..120
            const float* W = (n < 64) ? (Wl + (size_t)(kb + k) * 64 + n)
                                      : (Wr + (size_t)(kb + k) * 64 + (n - 64));
            float4 v0 = __ldg((const float4*)(W));
            float4 v1 = __ldg((const float4*)(W + 4));
            Bs2[k][n + 0] = pack2(v0.x, v0.x);
            Bs2[k][n + 1] = pack2(v0.y, v0.y);
            Bs2[k][n + 2] = pack2(v0.z, v0.z);
            Bs2[k][n + 3] = pack2(v0.w, v0.w);
            Bs2[k][n + 4] = pack2(v1.x, v1.x);
            Bs2[k][n + 5] = pack2(v1.y, v1.y);
            Bs2[k][n + 6] = pack2(v1.z, v1.z);
            Bs2[k][n + 7] = pack2(v1.w, v1.w);
        }
        __syncthreads();
        #pragma unroll
        for (int k = 0; k < 16; ++k) {
            u64 Ap[4];
            #pragma unroll
            for (int i = 0; i < 4; ++i)
                Ap[i] = *(const u64*)&As[k][ty * 8 + 2 * i];
            #pragma unroll
            for (int j = 0; j < 8; ++j) {
                u64 Bv = Bs2[k][j * 16 + tx];
                fma2(acc[0][j], Ap[0], Bv);
                fma2(acc[1][j], Ap[1], Bv);
                fma2(acc[2][j], Ap[2], Bv);
                fma2(acc[3][j], Ap[3], Bv);
            }
        }
    }

    #pragma unroll
    for (int j = 0; j < 8; ++j) {
        int col = j * 16 + tx;
        bool isSelf = (col >= 64);
        int nc = isSelf ? (col - 64) : col;
        float bb = isSelf ? b[nc] : 0.f;
        float* dst = isSelf ? g_self : g_y1;
        #pragma unroll
        for (int i = 0; i < 4; ++i) {
            float v0, v1;
            unpack2(acc[i][j], v0, v1);
            int r0 = m0 + ty * 8 + 2 * i;
            if (r0 < NN)     dst[(size_t)r0 * HH + nc]       = v0 + bb;
            if (r0 + 1 < NN) dst[(size_t)(r0 + 1) * HH + nc] = v1 + bb;
        }
    }
}

// ---------------------------------------------------------------------------
// agg1 + ReLU: h[n] = relu( invdeg * sum_{s} y1[s] + self[n] )
// Warp per node; PAIRED-EDGE float4 gather: lanes 0-15 cover edge e's row
// (16 x float4 = 256B), lanes 16-31 cover edge e+1's row. One LDG.128
// instruction serves two edges. Final cross-half combine via 4 shfl_xor.
// ---------------------------------------------------------------------------
__global__ void k_agg1(void) {
    int w = (blockIdx.x * blockDim.x + threadIdx.x) >> 5;
    int lane = threadIdx.x & 31;
    if (w >= NN) return;
    int half = lane >> 4;     // which edge of the pair
    int fl = lane & 15;       // float4 index within row
    int beg = g_rowptr[w], n = g_cnt[w];
    const float4* yb = (const float4*)g_y1;   // 16 float4 per row

    float4 a0 = make_float4(0.f, 0.f, 0.f, 0.f);
    float4 a1 = make_float4(0.f, 0.f, 0.f, 0.f);
    int e = 0;
    for (; e + 4 <= n; e += 4) {
        int s0 = g_srcs[beg + e + half];
        int s1 = g_srcs[beg + e + 2 + half];
        float4 v0 = __ldg(yb + (size_t)s0 * 16 + fl);
        float4 v1 = __ldg(yb + (size_t)s1 * 16 + fl);
        a0.x += v0.x; a0.y += v0.y; a0.z += v0.z; a0.w += v0.w;
        a1.x += v1.x; a1.y += v1.y; a1.z += v1.z; a1.w += v1.w;
    }
    for (; e + 2 <= n; e += 2) {
        int s0 = g_srcs[beg + e + half];
        float4 v0 = __ldg(yb + (size_t)s0 * 16 + fl);
        a0.x += v0.x; a0.y += v0.y; a0.z += v0.z; a0.w += v0.w;
    }
    if (e < n && half == 0) {
        int s0 = g_srcs[beg + e];
        float4 v0 = __ldg(yb + (size_t)s0 * 16 + fl);
        a0.x += v0.x; a0.y += v0.y; a0.z += v0.z; a0.w += v0.w;
    }
    a0.x += a1.x; a0.y += a1.y; a0.z += a1.z; a0.w += a1.w;
    a0.x += __shfl_xor_sync(0xffffffffu, a0.x, 16);
    a0.y += __shfl_xor_sync(0xffffffffu, a0.y, 16);
    a0.z += __shfl_xor_sync(0xffffffffu, a0.z, 16);
    a0.w += __shfl_xor_sync(0xffffffffu, a0.w, 16);
    if (half == 0) {
        float sc = g_invdeg[w];
        float4 s = ((const float4*)g_self)[(size_t)w * 16 + fl];
        float4 o;
        o.x = fmaxf(a0.x * sc + s.x, 0.f);
        o.y = fmaxf(a0.y * sc + s.y, 0.f);
        o.z = fmaxf(a0.z * sc + s.z, 0.f);
        o.w = fmaxf(a0.w * sc + s.w, 0.f);
        ((float4*)g_h)[(size_t)w * 16 + fl] = o;
    }
}

// ---------------------------------------------------------------------------
// agg2: g_agg2[n] = invdeg * sum_{s} h[s]   (same paired-edge float4 gather)
// ---------------------------------------------------------------------------
__global__ void k_agg2(void) {
    int w = (blockIdx.x * blockDim.x + threadIdx.x) >> 5;
    int lane = threadIdx.x & 31;
    if (w >= NN) return;
    int half = lane >> 4;
    int fl = lane & 15;
    int beg = g_rowptr[w], n = g_cnt[w];
    const float4* hb = (const float4*)g_h;

    float4 a0 = make_float4(0.f, 0.f, 0.f, 0.f);
    float4 a1 = make_float4(0.f, 0.f, 0.f, 0.f);
    int e = 0;
    for (; e + 4 <= n; e += 4) {
        int s0 = g_srcs[beg + e + half];
        int s1 = g_srcs[beg + e + 2 + half];
        float4 v0 = __ldg(hb + (size_t)s0 * 16 + fl);
        float4 v1 = __ldg(hb + (size_t)s1 * 16 + fl);
        a0.x += v0.x; a0.y += v0.y; a0.z += v0.z; a0.w += v0.w;
        a1.x += v1.x; a1.y += v1.y; a1.z += v1.z; a1.w += v1.w;
    }
    for (; e + 2 <= n; e += 2) {
        int s0 = g_srcs[beg + e + half];
        float4 v0 = __ldg(hb + (size_t)s0 * 16 + fl);
        a0.x += v0.x; a0.y += v0.y; a0.z += v0.z; a0.w += v0.w;
    }
    if (e < n && half == 0) {
        int s0 = g_srcs[beg + e];
        float4 v0 = __ldg(hb + (size_t)s0 * 16 + fl);
        a0.x += v0.x; a0.y += v0.y; a0.z += v0.z; a0.w += v0.w;
    }
    a0.x += a1.x; a0.y += a1.y; a0.z += a1.z; a0.w += a1.w;
    a0.x += __shfl_xor_sync(0xffffffffu, a0.x, 16);
    a0.y += __shfl_xor_sync(0xffffffffu, a0.y, 16);
    a0.z += __shfl_xor_sync(0xffffffffu, a0.z, 16);
    a0.w += __shfl_xor_sync(0xffffffffu, a0.w, 16);
    if (half == 0) {
        float sc = g_invdeg[w];
        float4 o;
        o.x = a0.x * sc; o.y = a0.y * sc;
        o.z = a0.z * sc; o.w = a0.w * sc;
        ((float4*)g_agg2)[(size_t)w * 16 + fl] = o;
    }
}

// ---------------------------------------------------------------------------
// GEMM2 + fused log_softmax (warp per node), packed f32x2.
// ---------------------------------------------------------------------------
__global__ void k_gemm2(const float* __restrict__ Wl,
                        const float* __restrict__ Wr,
                        const float* __restrict__ b,
                        float* __restrict__ out) {
    __shared__ float2 sW[64 * 40];
    __shared__ float sb[40];
    int tid = threadIdx.x;
    for (int i = tid; i < 64 * 40; i += blockDim.x)
        sW[i] = make_float2(Wl[i], Wr[i]);
    if (tid < 40) sb[tid] = b[tid];
    __syncthreads();

    int w = (blockIdx.x * blockDim.x + tid) >> 5;
    int lane = tid & 31;
    if (w >= NN) return;
    bool lo8 = (lane < 8);

    const float* ag = g_agg2 + (size_t)w * HH;
    const float* hr = g_h    + (size_t)w * HH;
    float a0 = ag[lane], a1 = ag[lane + 32];
    float h0 = hr[lane], h1 = hr[lane + 32];

    u64 acc0 = 0, acc1 = 0;
    #pragma unroll
    for (int k = 0; k < 32; ++k) {
        float av = __shfl_sync(0xffffffffu, a0, k);
        float hv = __shfl_sync(0xffffffffu, h0, k);
        u64 p = pack2(av, hv);
        fma2(acc0, p, *(const u64*)&sW[k * 40 + lane]);
        if (lo8) fma2(acc1, p, *(const u64*)&sW[k * 40 + 32 + lane]);
    }
    #pragma unroll
    for (int k = 0; k < 32; ++k) {
        float av = __shfl_sync(0xffffffffu, a1, k);
        float hv = __shfl_sync(0xffffffffu, h1, k);
        u64 p = pack2(av, hv);
        int kr = k + 32;
        fma2(acc0, p, *(const u64*)&sW[kr * 40 + lane]);
        if (lo8) fma2(acc1, p, *(const u64*)&sW[kr * 40 + 32 + lane]);
    }

    float u0, v0, u1, v1;
    unpack2(acc0, u0, v0);
    unpack2(acc1, u1, v1);
    float z0 = u0 + v0 + sb[lane];
    float z1 = lo8 ? (u1 + v1 + sb[32 + lane]) : -INFINITY;

    float m = fmaxf(z0, z1);
    #pragma unroll
    for (int o = 16; o; o >>= 1) m = fmaxf(m, __shfl_xor_sync(0xffffffffu, m, o));
    float e = expf(z0 - m) + (lo8 ? expf(z1 - m) : 0.f);
    #pragma unroll
    for (int o = 16; o; o >>= 1) e += __shfl_xor_sync(0xffffffffu, e, o);
    float lse = logf(e) + m;

    out[(size_t)w * CC + lane] = z0 - lse;
    if (lo8) out[(size_t)w * CC + 32 + lane] = z1 - lse;
}

// ---------------------------------------------------------------------------
extern "C" void kernel_launch(void* const* d_in, const int* in_sizes, int n_in,
                              void* d_out, int out_size) {
    const float* x   = (const float*)d_in[0];
    const void*  ei  = d_in[1];
    const float* W1l = (const float*)d_in[2];
    const float* W1r = (const float*)d_in[3];
    const float* b1  = (const float*)d_in[4];
    const float* W2l = (const float*)d_in[5];
    const float* W2r = (const float*)d_in[6];
    const float* b2  = (const float*)d_in[7];
    float* out = (float*)d_out;

    int nE = in_sizes[1] / 2;
    int eBlocks = (nE + 255) / 256;
    int nWarpBlocks = (NN * 32 + 255) / 256;

    k_detzero<<<(NN + 255) / 256, 256>>>(ei);            // 1
    k_hist<<<eBlocks, 256>>>(ei, nE);                    // 2
    k_scan1<<<NB, 256>>>();                              // 3
    k_gemm1<<<(NN + 127) / 128, 256>>>(x, W1l, W1r, b1); // 4 <- ncu window
    k_scan23<<<NB, 256>>>();                             // 5
    k_fill<<<eBlocks, 256>>>(ei, nE);                    // 6
    k_agg1<<<nWarpBlocks, 256>>>();                      // 7
    k_agg2<<<nWarpBlocks, 256>>>();                      // 8
    k_gemm2<<<(NN + 7) / 8, 256>>>(W2l, W2r, b2, out);   // 9
}

// round 12
// speedup vs baseline: 1.0580x; 1.0396x over previous
#include <cuda_runtime.h>
#include <math.h>

#define NN 100000
#define DD 128
#define HH 64
#define CC 40
#define NB 391          // ceil(NN/256) scan blocks

typedef unsigned long long u64;

// ---- scratch (__device__ globals per harness rules) ----
__device__ float g_y1[(size_t)NN * HH];     // x @ W1l            25.6 MB
__device__ float g_self[(size_t)NN * HH];   // x @ W1r + b1       25.6 MB
__device__ float g_h[(size_t)NN * HH];      // layer-1 output     25.6 MB
__device__ float g_agg2[(size_t)NN * HH];   // mean(h[nbrs])      25.6 MB
__device__ int   g_cnt[NN];
__device__ int   g_rowptr[NN];
__device__ int   g_cur[NN];
__device__ float g_invdeg[NN];
__device__ int   g_srcs[2000000];
__device__ int   g_exc[NB * 256];
__device__ int   g_bsum[512];
__device__ int   g_is64;

// ---- f32x2 packed-math helpers (sm_103a FFMA2) ----
__device__ __forceinline__ u64 pack2(float lo, float hi) {
    u64 r;
    asm("mov.b64 %0, {%1, %2};" : "=l"(r) : "f"(lo), "f"(hi));
    return r;
}
__device__ __forceinline__ void unpack2(u64 v, float& lo, float& hi) {
    asm("mov.b64 {%0, %1}, %2;" : "=f"(lo), "=f"(hi) : "l"(v));
}
__device__ __forceinline__ void fma2(u64& d, u64 a, u64 b) {
    asm("fma.rn.f32x2 %0, %1, %2, %0;" : "+l"(d) : "l"(a), "l"(b));
}

// ---------------------------------------------------------------------------
__global__ void k_detzero(const void* __restrict__ ei) {
    int i = blockIdx.x * blockDim.x + threadIdx.x;
    if (i < NN) g_cnt[i] = 0;
    if (blockIdx.x == 0) {
        if (threadIdx.x == 0) g_is64 = 1;
        __syncthreads();
        if (threadIdx.x < 128) {
            long long v = ((const long long*)ei)[threadIdx.x];
            if (v < 0 || v >= NN) atomicAnd(&g_is64, 0);
        }
    }
}

__global__ void k_hist(const void* __restrict__ ei, int nE) {
    int e = blockIdx.x * blockDim.x + threadIdx.x;
    if (e >= nE) return;
    int d = g_is64 ? (int)((const long long*)ei)[nE + e]
                   : ((const int*)ei)[nE + e];
    atomicAdd(&g_cnt[d], 1);
}

__global__ void k_scan1() {
    __shared__ int sh[256];
    int t = threadIdx.x, b = blockIdx.x;
    int i = b * 256 + t;
    int v = (i < NN) ? g_cnt[i] : 0;
    sh[t] = v;
    __syncthreads();
    #pragma unroll
    for (int off = 1; off < 256; off <<= 1) {
        int u = (t >= off) ? sh[t - off] : 0;
        __syncthreads();
        sh[t] += u;
        __syncthreads();
    }
    if (i < NN) g_exc[i] = sh[t] - v;
    if (t == 255) g_bsum[b] = sh[t];
}

__global__ void k_scan23() {
    __shared__ int red[8];
    __shared__ int boff;
    int b = blockIdx.x, t = threadIdx.x;
    int v = 0;
    if (t < b) v = g_bsum[t];
    if (t + 256 < b) v += g_bsum[t + 256];
    #pragma unroll
    for (int o = 16; o; o >>= 1) v += __shfl_xor_sync(0xffffffffu, v, o);
    if ((t & 31) == 0) red[t >> 5] = v;
    __syncthreads();
    if (t == 0) {
        int s = 0;
        #pragma unroll
        for (int j = 0; j < 8; ++j) s += red[j];
        boff = s;
    }
    __syncthreads();
    int i = b * 256 + t;
    if (i < NN) {
        int row = g_exc[i] + boff;
        g_rowptr[i] = row;
        g_cur[i] = row;
        g_invdeg[i] = 1.0f / fmaxf((float)g_cnt[i], 1.0f);
    }
}

__global__ void k_fill(const void* __restrict__ ei, int nE) {
    int e = blockIdx.x * blockDim.x + threadIdx.x;
    if (e >= nE) return;
    int s, d;
    if (g_is64) {
        const long long* p = (const long long*)ei;
        s = (int)p[e]; d = (int)p[nE + e];
    } else {
        const int* p = (const int*)ei;
        s = p[e]; d = p[nE + e];
    }
    int pos = atomicAdd(&g_cur[d], 1);
    g_srcs[pos] = s;
}

// ---------------------------------------------------------------------------
// GEMM1 v5: r9 kernel + double-buffered smem software pipeline.
// [y1 | self+b1] = x[N,128] @ [W1l | W1r][128,128]
// 128x128 tile, 256 threads, 8x8 microtile, K-chunk 16, 2 smem buffers.
// Per phase: LDG(chunk c+1) -> compute k0..7 -> STS(buf^1) -> compute k8..15
// -> sync. One sync per phase; GMEM latency hidden under compute.
// ---------------------------------------------------------------------------
__global__ void __launch_bounds__(256, 2)
k_gemm1(const float* __restrict__ x,
        const float* __restrict__ Wl,
        const float* __restrict__ Wr,
        const float* __restrict__ b) {
    __shared__ float As[2][16][130];   // [buf][k][m], pitch 130 (u64-aligned)
    __shared__ u64   Bs2[2][16][128];  // [buf][k][n] duplicated (b,b)

    int tid = threadIdx.x;
    int tx = tid & 15;        // col lane: cols {tx, tx+16, ..., tx+112}
    int ty = tid >> 4;        // row group: rows ty*8 .. ty*8+7
    int m0 = blockIdx.x * 128;

    // loader indices (fixed per thread)
    int am  = tid >> 2;             // 0..63
    int akk = (tid & 3) * 4;        // 0,4,8,12
    int amg0 = min(m0 + am, NN - 1);
    int amg1 = min(m0 + am + 64, NN - 1);
    int bk = tid >> 4;              // 0..15
    int bn = (tid & 15) * 8;        // 0..120

    u64 acc[4][8] = {};
    float4 pa0, pa1, pb0, pb1;

    // ---- prefetch + store chunk 0 into buf 0
    pa0 = __ldg((const float4*)(x + (size_t)amg0 * DD + akk));
    pa1 = __ldg((const float4*)(x + (size_t)amg1 * DD + akk));
    {
        const float* W = (bn < 64) ? (Wl + (size_t)bk * 64 + bn)
                                   : (Wr + (size_t)bk * 64 + (bn - 64));
        pb0 = __ldg((const float4*)(W));
        pb1 = __ldg((const float4*)(W + 4));
    }
    As[0][akk + 0][am] = pa0.x; As[0][akk + 1][am] = pa0.y;
    As[0][akk + 2][am] = pa0.z; As[0][akk + 3][am] = pa0.w;
    As[0][akk + 0][am + 64] = pa1.x; As[0][akk + 1][am + 64] = pa1.y;
    As[0][akk + 2][am + 64] = pa1.z; As[0][akk + 3][am + 64] = pa1.w;
    Bs2[0][bk][bn + 0] = pack2(pb0.x, pb0.x);
    Bs2[0][bk][bn + 1] = pack2(pb0.y, pb0.y);
    Bs2[0][bk][bn + 2] = pack2(pb0.z, pb0.z);
    Bs2[0][bk][bn + 3] = pack2(pb0.w, pb0.w);
    Bs2[0][bk][bn + 4] = pack2(pb1.x, pb1.x);
    Bs2[0][bk][bn + 5] = pack2(pb1.y, pb1.y);
    Bs2[0][bk][bn + 6] = pack2(pb1.z, pb1.z);
    Bs2[0][bk][bn + 7] = pack2(pb1.w, pb1.w);
    __syncthreads();

    #pragma unroll 1
    for (int c = 0; c < 8; ++c) {
        int p = c & 1;
        const float (*Ab)[130] = As[p];
        const u64   (*Bb)[128] = Bs2[p];

        // issue prefetch LDGs for chunk c+1
        if (c < 7) {
            int kb = (c + 1) * 16;
            pa0 = __ldg((const float4*)(x + (size_t)amg0 * DD + kb + akk));
            pa1 = __ldg((const float4*)(x + (size_t)amg1 * DD + kb + akk));
            const float* W = (bn < 64) ? (Wl + (size_t)(kb + bk) * 64 + bn)
                                       : (Wr + (size_t)(kb + bk) * 64 + (bn - 64));
            pb0 = __ldg((const float4*)(W));
            pb1 = __ldg((const float4*)(W + 4));
        }

        // compute k = 0..7 on buf p
        #pragma unroll
        for (int k = 0; k < 8; ++k) {
            u64 Ap[4];
            #pragma unroll
            for (int i = 0; i < 4; ++i)
                Ap[i] = *(const u64*)&Ab[k][ty * 8 + 2 * i];
            #pragma unroll
            for (int j = 0; j < 8; ++j) {
                u64 Bv = Bb[k][j * 16 + tx];
                fma2(acc[0][j], Ap[0], Bv);
                fma2(acc[1][j], Ap[1], Bv);
                fma2(acc[2][j], Ap[2], Bv);
                fma2(acc[3][j], Ap[3], Bv);
            }
        }

        // stash prefetched chunk into the other buffer (mid-phase)
        if (c < 7) {
            int q = p ^ 1;
            As[q][akk + 0][am] = pa0.x; As[q][akk + 1][am] = pa0.y;
            As[q][akk + 2][am] = pa0.z; As[q][akk + 3][am] = pa0.w;
            As[q][akk + 0][am + 64] = pa1.x; As[q][akk + 1][am + 64] = pa1.y;
            As[q][akk + 2][am + 64] = pa1.z; As[q][akk + 3][am + 64] = pa1.w;
            Bs2[q][bk][bn + 0] = pack2(pb0.x, pb0.x);
            Bs2[q][bk][bn + 1] = pack2(pb0.y, pb0.y);
            Bs2[q][bk][bn + 2] = pack2(pb0.z, pb0.z);
            Bs2[q][bk][bn + 3] = pack2(pb0.w, pb0.w);
            Bs2[q][bk][bn + 4] = pack2(pb1.x, pb1.x);
            Bs2[q][bk][bn + 5] = pack2(pb1.y, pb1.y);
            Bs2[q][bk][bn + 6] = pack2(pb1.z, pb1.z);
            Bs2[q][bk][bn + 7] = pack2(pb1.w, pb1.w);
        }

        // compute k = 8..15 on buf p
        #pragma unroll
        for (int k = 8; k < 16; ++k) {
            u64 Ap[4];
            #pragma unroll
            for (int i = 0; i < 4; ++i)
                Ap[i] = *(const u64*)&Ab[k][ty * 8 + 2 * i];
            #pragma unroll
            for (int j = 0; j < 8; ++j) {
                u64 Bv = Bb[k][j * 16 + tx];
                fma2(acc[0][j], Ap[0], Bv);
                fma2(acc[1][j], Ap[1], Bv);
                fma2(acc[2][j], Ap[2], Bv);
                fma2(acc[3][j], Ap[3], Bv);
            }
        }
        __syncthreads();
    }

    // epilogue: col<64 -> g_y1 ; col>=64 -> g_self (+b1)
    #pragma unroll
    for (int j = 0; j < 8; ++j) {
        int col = j * 16 + tx;
        bool isSelf = (col >= 64);
        int nc = isSelf ? (col - 64) : col;
        float bb = isSelf ? b[nc] : 0.f;
        float* dst = isSelf ? g_self : g_y1;
        #pragma unroll
        for (int i = 0; i < 4; ++i) {
            float v0, v1;
            unpack2(acc[i][j], v0, v1);
            int r0 = m0 + ty * 8 + 2 * i;
            if (r0 < NN)     dst[(size_t)r0 * HH + nc]       = v0 + bb;
            if (r0 + 1 < NN) dst[(size_t)(r0 + 1) * HH + nc] = v1 + bb;
        }
    }
}

// ---------------------------------------------------------------------------
// agg1 + ReLU (r9 measured version): warp per node, float2 lanes, 2-unrolled.
// ---------------------------------------------------------------------------
__global__ void k_agg1(void) {
    int w = (blockIdx.x * blockDim.x + threadIdx.x) >> 5;
    int lane = threadIdx.x & 31;
    if (w >= NN) return;
    int beg = g_rowptr[w], n = g_cnt[w];
    const float2* yb = (const float2*)g_y1;
    float2 a0 = make_float2(0.f, 0.f), a1 = make_float2(0.f, 0.f);
    int e = 0;
    for (; e + 1 < n; e += 2) {
        int s0 = g_srcs[beg + e];
        int s1 = g_srcs[beg + e + 1];
        float2 v0 = __ldg(yb + (size_t)s0 * 32 + lane);
        float2 v1 = __ldg(yb + (size_t)s1 * 32 + lane);
        a0.x += v0.x; a0.y += v0.y;
        a1.x += v1.x; a1.y += v1.y;
    }
    if (e < n) {
        int s0 = g_srcs[beg + e];
        float2 v0 = __ldg(yb + (size_t)s0 * 32 + lane);
        a0.x += v0.x; a0.y += v0.y;
    }
    float sc = g_invdeg[w];
    float2 s = ((const float2*)g_self)[(size_t)w * 32 + lane];
    float2 o;
    o.x = fmaxf((a0.x + a1.x) * sc + s.x, 0.f);
    o.y = fmaxf((a0.y + a1.y) * sc + s.y, 0.f);
    ((float2*)g_h)[(size_t)w * 32 + lane] = o;
}

// ---------------------------------------------------------------------------
// agg2 (r9 measured version): g_agg2[n] = invdeg * sum_{s} h[s]
// ---------------------------------------------------------------------------
__global__ void k_agg2(void) {
    int w = (blockIdx.x * blockDim.x + threadIdx.x) >> 5;
    int lane = threadIdx.x & 31;
    if (w >= NN) return;
    int beg = g_rowptr[w], n = g_cnt[w];
    const float2* hb = (const float2*)g_h;
    float2 a0 = make_float2(0.f, 0.f), a1 = make_float2(0.f, 0.f);
    int e = 0;
    for (; e + 1 < n; e += 2) {
        int s0 = g_srcs[beg + e];
        int s1 = g_srcs[beg + e + 1];
        float2 v0 = __ldg(hb + (size_t)s0 * 32 + lane);
        float2 v1 = __ldg(hb + (size_t)s1 * 32 + lane);
        a0.x += v0.x; a0.y += v0.y;
        a1.x += v1.x; a1.y += v1.y;
    }
    if (e < n) {
        int s0 = g_srcs[beg + e];
        float2 v0 = __ldg(hb + (size_t)s0 * 32 + lane);
        a0.x += v0.x; a0.y += v0.y;
    }
    float sc = g_invdeg[w];
    float2 o;
    o.x = (a0.x + a1.x) * sc;
    o.y = (a0.y + a1.y) * sc;
    ((float2*)g_agg2)[(size_t)w * 32 + lane] = o;
}

// ---------------------------------------------------------------------------
// GEMM2 + fused log_softmax (warp per node), packed f32x2.
// ---------------------------------------------------------------------------
__global__ void k_gemm2(const float* __restrict__ Wl,
                        const float* __restrict__ Wr,
                        const float* __restrict__ b,
                        float* __restrict__ out) {
    __shared__ float2 sW[64 * 40];
    __shared__ float sb[40];
    int tid = threadIdx.x;
    for (int i = tid; i < 64 * 40; i += blockDim.x)
        sW[i] = make_float2(Wl[i], Wr[i]);
    if (tid < 40) sb[tid] = b[tid];
    __syncthreads();

    int w = (blockIdx.x * blockDim.x + tid) >> 5;
    int lane = tid & 31;
    if (w >= NN) return;
    bool lo8 = (lane < 8);

    const float* ag = g_agg2 + (size_t)w * HH;
    const float* hr = g_h    + (size_t)w * HH;
    float a0 = ag[lane], a1 = ag[lane + 32];
    float h0 = hr[lane], h1 = hr[lane + 32];

    u64 acc0 = 0, acc1 = 0;
    #pragma unroll
    for (int k = 0; k < 32; ++k) {
        float av = __shfl_sync(0xffffffffu, a0, k);
        float hv = __shfl_sync(0xffffffffu, h0, k);
        u64 p = pack2(av, hv);
        fma2(acc0, p, *(const u64*)&sW[k * 40 + lane]);
        if (lo8) fma2(acc1, p, *(const u64*)&sW[k * 40 + 32 + lane]);
    }
    #pragma unroll
    for (int k = 0; k < 32; ++k) {
        float av = __shfl_sync(0xffffffffu, a1, k);
        float hv = __shfl_sync(0xffffffffu, h1, k);
        u64 p = pack2(av, hv);
        int kr = k + 32;
        fma2(acc0, p, *(const u64*)&sW[kr * 40 + lane]);
        if (lo8) fma2(acc1, p, *(const u64*)&sW[kr * 40 + 32 + lane]);
    }

    float u0, v0, u1, v1;
    unpack2(acc0, u0, v0);
    unpack2(acc1, u1, v1);
    float z0 = u0 + v0 + sb[lane];
    float z1 = lo8 ? (u1 + v1 + sb[32 + lane]) : -INFINITY;

    float m = fmaxf(z0, z1);
    #pragma unroll
    for (int o = 16; o; o >>= 1) m = fmaxf(m, __shfl_xor_sync(0xffffffffu, m, o));
    float e = expf(z0 - m) + (lo8 ? expf(z1 - m) : 0.f);
    #pragma unroll
    for (int o = 16; o; o >>= 1) e += __shfl_xor_sync(0xffffffffu, e, o);
    float lse = logf(e) + m;

    out[(size_t)w * CC + lane] = z0 - lse;
    if (lo8) out[(size_t)w * CC + 32 + lane] = z1 - lse;
}

// ---------------------------------------------------------------------------
extern "C" void kernel_launch(void* const* d_in, const int* in_sizes, int n_in,
                              void* d_out, int out_size) {
    const float* x   = (const float*)d_in[0];
    const void*  ei  = d_in[1];
    const float* W1l = (const float*)d_in[2];
    const float* W1r = (const float*)d_in[3];
    const float* b1  = (const float*)d_in[4];
    const float* W2l = (const float*)d_in[5];
    const float* W2r = (const float*)d_in[6];
    const float* b2  = (const float*)d_in[7];
    float* out = (float*)d_out;

    int nE = in_sizes[1] / 2;
    int eBlocks = (nE + 255) / 256;
    int nWarpBlocks = (NN * 32 + 255) / 256;

    k_detzero<<<(NN + 255) / 256, 256>>>(ei);            // 1
    k_hist<<<eBlocks, 256>>>(ei, nE);                    // 2
    k_scan1<<<NB, 256>>>();                              // 3
    k_gemm1<<<(NN + 127) / 128, 256>>>(x, W1l, W1r, b1); // 4 <- ncu window
    k_scan23<<<NB, 256>>>();                             // 5
    k_fill<<<eBlocks, 256>>>(ei, nE);                    // 6
    k_agg1<<<nWarpBlocks, 256>>>();                      // 7
    k_agg2<<<nWarpBlocks, 256>>>();                      // 8
    k_gemm2<<<(NN + 7) / 8, 256>>>(W2l, W2r, b2, out);   // 9
}

// round 13
// speedup vs baseline: 1.0590x; 1.0010x over previous
#include <cuda_runtime.h>
#include <math.h>

#define NN 100000
#define DD 128
#define HH 64
#define CC 40
#define NB 391          // ceil(NN/256) scan blocks

typedef unsigned long long u64;

// ---- scratch (__device__ globals per harness rules) ----
__device__ float g_y1[(size_t)NN * HH];     // x @ W1l            25.6 MB
__device__ float g_self[(size_t)NN * HH];   // x @ W1r + b1       25.6 MB
__device__ float g_h[(size_t)NN * HH];      // layer-1 output     25.6 MB
__device__ float g_agg2[(size_t)NN * HH];   // mean(h[nbrs])      25.6 MB
__device__ int   g_cnt[NN];
__device__ int   g_rowptr[NN];
__device__ int   g_cur[NN];
__device__ float g_invdeg[NN];
__device__ int   g_srcs[2000000];
__device__ int   g_exc[NB * 256];
__device__ int   g_bsum[512];
__device__ int   g_is64;

// ---- f32x2 packed-math helpers (sm_103a FFMA2) ----
__device__ __forceinline__ u64 pack2(float lo, float hi) {
    u64 r;
    asm("mov.b64 %0, {%1, %2};" : "=l"(r) : "f"(lo), "f"(hi));
    return r;
}
__device__ __forceinline__ void unpack2(u64 v, float& lo, float& hi) {
    asm("mov.b64 {%0, %1}, %2;" : "=f"(lo), "=f"(hi) : "l"(v));
}
__device__ __forceinline__ void fma2(u64& d, u64 a, u64 b) {
    asm("fma.rn.f32x2 %0, %1, %2, %0;" : "+l"(d) : "l"(a), "l"(b));
}

// ---------------------------------------------------------------------------
__global__ void k_detzero(const void* __restrict__ ei) {
    int i = blockIdx.x * blockDim.x + threadIdx.x;
    if (i < NN) g_cnt[i] = 0;
    if (blockIdx.x == 0) {
        if (threadIdx.x == 0) g_is64 = 1;
        __syncthreads();
        if (threadIdx.x < 128) {
            long long v = ((const long long*)ei)[threadIdx.x];
            if (v < 0 || v >= NN) atomicAnd(&g_is64, 0);
        }
    }
}

__global__ void k_hist(const void* __restrict__ ei, int nE) {
    int e = blockIdx.x * blockDim.x + threadIdx.x;
    if (e >= nE) return;
    int d = g_is64 ? (int)((const long long*)ei)[nE + e]
                   : ((const int*)ei)[nE + e];
    atomicAdd(&g_cnt[d], 1);
}

__global__ void k_scan1() {
    __shared__ int sh[256];
    int t = threadIdx.x, b = blockIdx.x;
    int i = b * 256 + t;
    int v = (i < NN) ? g_cnt[i] : 0;
    sh[t] = v;
    __syncthreads();
    #pragma unroll
    for (int off = 1; off < 256; off <<= 1) {
        int u = (t >= off) ? sh[t - off] : 0;
        __syncthreads();
        sh[t] += u;
        __syncthreads();
    }
    if (i < NN) g_exc[i] = sh[t] - v;
    if (t == 255) g_bsum[b] = sh[t];
}

__global__ void k_scan23() {
    __shared__ int red[8];
    __shared__ int boff;
    int b = blockIdx.x, t = threadIdx.x;
    int v = 0;
    if (t < b) v = g_bsum[t];
    if (t + 256 < b) v += g_bsum[t + 256];
    #pragma unroll
    for (int o = 16; o; o >>= 1) v += __shfl_xor_sync(0xffffffffu, v, o);
    if ((t & 31) == 0) red[t >> 5] = v;
    __syncthreads();
    if (t == 0) {
        int s = 0;
        #pragma unroll
        for (int j = 0; j < 8; ++j) s += red[j];
        boff = s;
    }
    __syncthreads();
    int i = b * 256 + t;
    if (i < NN) {
        int row = g_exc[i] + boff;
        g_rowptr[i] = row;
        g_cur[i] = row;
        g_invdeg[i] = 1.0f / fmaxf((float)g_cnt[i], 1.0f);
    }
}

__global__ void k_fill(const void* __restrict__ ei, int nE) {
    int e = blockIdx.x * blockDim.x + threadIdx.x;
    if (e >= nE) return;
    int s, d;
    if (g_is64) {
        const long long* p = (const long long*)ei;
        s = (int)p[e]; d = (int)p[nE + e];
    } else {
        const int* p = (const int*)ei;
        s = p[e]; d = p[nE + e];
    }
    int pos = atomicAdd(&g_cur[d], 1);
    g_srcs[pos] = s;
}

// ---------------------------------------------------------------------------
// GEMM1 (r12 measured version): double-buffered pipeline, 128x128 tile,
// 256 threads, 8x8 microtile, K-chunk 16.
// ---------------------------------------------------------------------------
__global__ void __launch_bounds__(256, 2)
k_gemm1(const float* __restrict__ x,
        const float* __restrict__ Wl,
        const float* __restrict__ Wr,
        const float* __restrict__ b) {
    __shared__ float As[2][16][130];
    __shared__ u64   Bs2[2][16][128];

    int tid = threadIdx.x;
    int tx = tid & 15;
    int ty = tid >> 4;
    int m0 = blockIdx.x * 128;

    int am  = tid >> 2;
    int akk = (tid & 3) * 4;
    int amg0 = min(m0 + am, NN - 1);
    int amg1 = min(m0 + am + 64, NN - 1);
    int bk = tid >> 4;
    int bn = (tid & 15) * 8;

    u64 acc[4][8] = {};
    float4 pa0, pa1, pb0, pb1;

    pa0 = __ldg((const float4*)(x + (size_t)amg0 * DD + akk));
    pa1 = __ldg((const float4*)(x + (size_t)amg1 * DD + akk));
    {
        const float* W = (bn < 64) ? (Wl + (size_t)bk * 64 + bn)
                                   : (Wr + (size_t)bk * 64 + (bn - 64));
        pb0 = __ldg((const float4*)(W));
        pb1 = __ldg((const float4*)(W + 4));
    }
    As[0][akk + 0][am] = pa0.x; As[0][akk + 1][am] = pa0.y;
    As[0][akk + 2][am] = pa0.z; As[0][akk + 3][am] = pa0.w;
    As[0][akk + 0][am + 64] = pa1.x; As[0][akk + 1][am + 64] = pa1.y;
    As[0][akk + 2][am + 64] = pa1.z; As[0][akk + 3][am + 64] = pa1.w;
    Bs2[0][bk][bn + 0] = pack2(pb0.x, pb0.x);
    Bs2[0][bk][bn + 1] = pack2(pb0.y, pb0.y);
    Bs2[0][bk][bn + 2] = pack2(pb0.z, pb0.z);
    Bs2[0][bk][bn + 3] = pack2(pb0.w, pb0.w);
    Bs2[0][bk][bn + 4] = pack2(pb1.x, pb1.x);
    Bs2[0][bk][bn + 5] = pack2(pb1.y, pb1.y);
    Bs2[0][bk][bn + 6] = pack2(pb1.z, pb1.z);
    Bs2[0][bk][bn + 7] = pack2(pb1.w, pb1.w);
    __syncthreads();

    #pragma unroll 1
    for (int c = 0; c < 8; ++c) {
        int p = c & 1;
        const float (*Ab)[130] = As[p];
        const u64   (*Bb)[128] = Bs2[p];

        if (c < 7) {
            int kb = (c + 1) * 16;
            pa0 = __ldg((const float4*)(x + (size_t)amg0 * DD + kb + akk));
            pa1 = __ldg((const float4*)(x + (size_t)amg1 * DD + kb + akk));
            const float* W = (bn < 64) ? (Wl + (size_t)(kb + bk) * 64 + bn)
                                       : (Wr + (size_t)(kb + bk) * 64 + (bn - 64));
            pb0 = __ldg((const float4*)(W));
            pb1 = __ldg((const float4*)(W + 4));
        }

        #pragma unroll
        for (int k = 0; k < 8; ++k) {
            u64 Ap[4];
            #pragma unroll
            for (int i = 0; i < 4; ++i)
                Ap[i] = *(const u64*)&Ab[k][ty * 8 + 2 * i];
            #pragma unroll
            for (int j = 0; j < 8; ++j) {
                u64 Bv = Bb[k][j * 16 + tx];
                fma2(acc[0][j], Ap[0], Bv);
                fma2(acc[1][j], Ap[1], Bv);
                fma2(acc[2][j], Ap[2], Bv);
                fma2(acc[3][j], Ap[3], Bv);
            }
        }

        if (c < 7) {
            int q = p ^ 1;
            As[q][akk + 0][am] = pa0.x; As[q][akk + 1][am] = pa0.y;
            As[q][akk + 2][am] = pa0.z; As[q][akk + 3][am] = pa0.w;
            As[q][akk + 0][am + 64] = pa1.x; As[q][akk + 1][am + 64] = pa1.y;
            As[q][akk + 2][am + 64] = pa1.z; As[q][akk + 3][am + 64] = pa1.w;
            Bs2[q][bk][bn + 0] = pack2(pb0.x, pb0.x);
            Bs2[q][bk][bn + 1] = pack2(pb0.y, pb0.y);
            Bs2[q][bk][bn + 2] = pack2(pb0.z, pb0.z);
            Bs2[q][bk][bn + 3] = pack2(pb0.w, pb0.w);
            Bs2[q][bk][bn + 4] = pack2(pb1.x, pb1.x);
            Bs2[q][bk][bn + 5] = pack2(pb1.y, pb1.y);
            Bs2[q][bk][bn + 6] = pack2(pb1.z, pb1.z);
            Bs2[q][bk][bn + 7] = pack2(pb1.w, pb1.w);
        }

        #pragma unroll
        for (int k = 8; k < 16; ++k) {
            u64 Ap[4];
            #pragma unroll
            for (int i = 0; i < 4; ++i)
                Ap[i] = *(const u64*)&Ab[k][ty * 8 + 2 * i];
            #pragma unroll
            for (int j = 0; j < 8; ++j) {
                u64 Bv = Bb[k][j * 16 + tx];
                fma2(acc[0][j], Ap[0], Bv);
                fma2(acc[1][j], Ap[1], Bv);
                fma2(acc[2][j], Ap[2], Bv);
                fma2(acc[3][j], Ap[3], Bv);
            }
        }
        __syncthreads();
    }

    #pragma unroll
    for (int j = 0; j < 8; ++j) {
        int col = j * 16 + tx;
        bool isSelf = (col >= 64);
        int nc = isSelf ? (col - 64) : col;
        float bb = isSelf ? b[nc] : 0.f;
        float* dst = isSelf ? g_self : g_y1;
        #pragma unroll
        for (int i = 0; i < 4; ++i) {
            float v0, v1;
            unpack2(acc[i][j], v0, v1);
            int r0 = m0 + ty * 8 + 2 * i;
            if (r0 < NN)     dst[(size_t)r0 * HH + nc]       = v0 + bb;
            if (r0 + 1 < NN) dst[(size_t)(r0 + 1) * HH + nc] = v1 + bb;
        }
    }
}

// ---------------------------------------------------------------------------
// agg1 + ReLU (measured version): warp per node, float2 lanes, 2-unrolled.
// ---------------------------------------------------------------------------
__global__ void k_agg1(void) {
    int w = (blockIdx.x * blockDim.x + threadIdx.x) >> 5;
    int lane = threadIdx.x & 31;
    if (w >= NN) return;
    int beg = g_rowptr[w], n = g_cnt[w];
    const float2* yb = (const float2*)g_y1;
    float2 a0 = make_float2(0.f, 0.f), a1 = make_float2(0.f, 0.f);
    int e = 0;
    for (; e + 1 < n; e += 2) {
        int s0 = g_srcs[beg + e];
        int s1 = g_srcs[beg + e + 1];
        float2 v0 = __ldg(yb + (size_t)s0 * 32 + lane);
        float2 v1 = __ldg(yb + (size_t)s1 * 32 + lane);
        a0.x += v0.x; a0.y += v0.y;
        a1.x += v1.x; a1.y += v1.y;
    }
    if (e < n) {
        int s0 = g_srcs[beg + e];
        float2 v0 = __ldg(yb + (size_t)s0 * 32 + lane);
        a0.x += v0.x; a0.y += v0.y;
    }
    float sc = g_invdeg[w];
    float2 s = ((const float2*)g_self)[(size_t)w * 32 + lane];
    float2 o;
    o.x = fmaxf((a0.x + a1.x) * sc + s.x, 0.f);
    o.y = fmaxf((a0.y + a1.y) * sc + s.y, 0.f);
    ((float2*)g_h)[(size_t)w * 32 + lane] = o;
}

// ---------------------------------------------------------------------------
// agg2 (measured version): g_agg2[n] = invdeg * sum_{s} h[s]
// ---------------------------------------------------------------------------
__global__ void k_agg2(void) {
    int w = (blockIdx.x * blockDim.x + threadIdx.x) >> 5;
    int lane = threadIdx.x & 31;
    if (w >= NN) return;
    int beg = g_rowptr[w], n = g_cnt[w];
    const float2* hb = (const float2*)g_h;
    float2 a0 = make_float2(0.f, 0.f), a1 = make_float2(0.f, 0.f);
    int e = 0;
    for (; e + 1 < n; e += 2) {
        int s0 = g_srcs[beg + e];
        int s1 = g_srcs[beg + e + 1];
        float2 v0 = __ldg(hb + (size_t)s0 * 32 + lane);
        float2 v1 = __ldg(hb + (size_t)s1 * 32 + lane);
        a0.x += v0.x; a0.y += v0.y;
        a1.x += v1.x; a1.y += v1.y;
    }
    if (e < n) {
        int s0 = g_srcs[beg + e];
        float2 v0 = __ldg(hb + (size_t)s0 * 32 + lane);
        a0.x += v0.x; a0.y += v0.y;
    }
    float sc = g_invdeg[w];
    float2 o;
    o.x = (a0.x + a1.x) * sc;
    o.y = (a0.y + a1.y) * sc;
    ((float2*)g_agg2)[(size_t)w * 32 + lane] = o;
}

// ---------------------------------------------------------------------------
// GEMM2 + fused log_softmax, PERSISTENT grid-stride version: weights are
// loaded into smem ONCE per block (1184 blocks -> 24MB fill traffic instead
// of 12.5k blocks -> 256MB), then each warp grid-strides over nodes.
// ---------------------------------------------------------------------------
__global__ void __launch_bounds__(256)
k_gemm2(const float* __restrict__ Wl,
        const float* __restrict__ Wr,
        const float* __restrict__ b,
        float* __restrict__ out) {
    __shared__ float2 sW[64 * 40];
    __shared__ float sb[40];
    int tid = threadIdx.x;
    for (int i = tid; i < 64 * 40; i += blockDim.x)
        sW[i] = make_float2(Wl[i], Wr[i]);
    if (tid < 40) sb[tid] = b[tid];
    __syncthreads();

    int lane = tid & 31;
    bool lo8 = (lane < 8);
    int gwarp = (blockIdx.x * blockDim.x + tid) >> 5;
    int nwarps = (gridDim.x * blockDim.x) >> 5;

    for (int w = gwarp; w < NN; w += nwarps) {
        const float* ag = g_agg2 + (size_t)w * HH;
        const float* hr = g_h    + (size_t)w * HH;
        float a0 = ag[lane], a1 = ag[lane + 32];
        float h0 = hr[lane], h1 = hr[lane + 32];

        u64 acc0 = 0, acc1 = 0;
        #pragma unroll
        for (int k = 0; k < 32; ++k) {
            float av = __shfl_sync(0xffffffffu, a0, k);
            float hv = __shfl_sync(0xffffffffu, h0, k);
            u64 p = pack2(av, hv);
            fma2(acc0, p, *(const u64*)&sW[k * 40 + lane]);
            if (lo8) fma2(acc1, p, *(const u64*)&sW[k * 40 + 32 + lane]);
        }
        #pragma unroll
        for (int k = 0; k < 32; ++k) {
            float av = __shfl_sync(0xffffffffu, a1, k);
            float hv = __shfl_sync(0xffffffffu, h1, k);
            u64 p = pack2(av, hv);
            int kr = k + 32;
            fma2(acc0, p, *(const u64*)&sW[kr * 40 + lane]);
            if (lo8) fma2(acc1, p, *(const u64*)&sW[kr * 40 + 32 + lane]);
        }

        float u0, v0, u1, v1;
        unpack2(acc0, u0, v0);
        unpack2(acc1, u1, v1);
        float z0 = u0 + v0 + sb[lane];
        float z1 = lo8 ? (u1 + v1 + sb[32 + lane]) : -INFINITY;

        float m = fmaxf(z0, z1);
        #pragma unroll
        for (int o = 16; o; o >>= 1) m = fmaxf(m, __shfl_xor_sync(0xffffffffu, m, o));
        float e = expf(z0 - m) + (lo8 ? expf(z1 - m) : 0.f);
        #pragma unroll
        for (int o = 16; o; o >>= 1) e += __shfl_xor_sync(0xffffffffu, e, o);
        float lse = logf(e) + m;

        out[(size_t)w * CC + lane] = z0 - lse;
        if (lo8) out[(size_t)w * CC + 32 + lane] = z1 - lse;
    }
}

// ---------------------------------------------------------------------------
extern "C" void kernel_launch(void* const* d_in, const int* in_sizes, int n_in,
                              void* d_out, int out_size) {
    const float* x   = (const float*)d_in[0];
    const void*  ei  = d_in[1];
    const float* W1l = (const float*)d_in[2];
    const float* W1r = (const float*)d_in[3];
    const float* b1  = (const float*)d_in[4];
    const float* W2l = (const float*)d_in[5];
    const float* W2r = (const float*)d_in[6];
    const float* b2  = (const float*)d_in[7];
    float* out = (float*)d_out;

    int nE = in_sizes[1] / 2;
    int eBlocks = (nE + 255) / 256;
    int nWarpBlocks = (NN * 32 + 255) / 256;

    k_detzero<<<(NN + 255) / 256, 256>>>(ei);            // 1
    k_hist<<<eBlocks, 256>>>(ei, nE);                    // 2
    k_scan1<<<NB, 256>>>();                              // 3
    k_gemm1<<<(NN + 127) / 128, 256>>>(x, W1l, W1r, b1); // 4 <- ncu window
    k_scan23<<<NB, 256>>>();                             // 5
    k_fill<<<eBlocks, 256>>>(ei, nE);                    // 6
    k_agg1<<<nWarpBlocks, 256>>>();                      // 7
    k_agg2<<<nWarpBlocks, 256>>>();                      // 8
    k_gemm2<<<1184, 256>>>(W2l, W2r, b2, out);           // 9 persistent
}

// round 14
// speedup vs baseline: 1.1041x; 1.0426x over previous
#include <cuda_runtime.h>
#include <cuda_fp16.h>
#include <math.h>

#define NN 100000
#define DD 128
#define HH 64
#define CC 40
#define NB 391          // ceil(NN/256) scan blocks

typedef unsigned long long u64;

// ---- scratch (__device__ globals per harness rules) ----
__device__ __half g_y1h[(size_t)NN * HH];    // x @ W1l        (fp16, 12.8 MB)
__device__ __half g_selfh[(size_t)NN * HH];  // x @ W1r + b1   (fp16, 12.8 MB)
__device__ __half g_hh[(size_t)NN * HH];     // layer-1 output (fp16, 12.8 MB)
__device__ float  g_agg2[(size_t)NN * HH];   // mean(h[nbrs])  (fp32, 25.6 MB)
__device__ int    g_cnt[NN];
__device__ int    g_rowptr[NN];
__device__ int    g_cur[NN];
__device__ float  g_invdeg[NN];
__device__ int    g_srcs[2000000];
__device__ int    g_exc[NB * 256];
__device__ int    g_bsum[512];
__device__ int    g_is64;

// ---- f32x2 packed-math helpers (sm_103a FFMA2) ----
__device__ __forceinline__ u64 pack2(float lo, float hi) {
    u64 r;
    asm("mov.b64 %0, {%1, %2};" : "=l"(r) : "f"(lo), "f"(hi));
    return r;
}
__device__ __forceinline__ void unpack2(u64 v, float& lo, float& hi) {
    asm("mov.b64 {%0, %1}, %2;" : "=f"(lo), "=f"(hi) : "l"(v));
}
__device__ __forceinline__ void fma2(u64& d, u64 a, u64 b) {
    asm("fma.rn.f32x2 %0, %1, %2, %0;" : "+l"(d) : "l"(a), "l"(b));
}

// ---------------------------------------------------------------------------
__global__ void k_detzero(const void* __restrict__ ei) {
    int i = blockIdx.x * blockDim.x + threadIdx.x;
    if (i < NN) g_cnt[i] = 0;
    if (blockIdx.x == 0) {
        if (threadIdx.x == 0) g_is64 = 1;
        __syncthreads();
        if (threadIdx.x < 128) {
            long long v = ((const long long*)ei)[threadIdx.x];
            if (v < 0 || v >= NN) atomicAnd(&g_is64, 0);
        }
    }
}

__global__ void k_hist(const void* __restrict__ ei, int nE) {
    int e = blockIdx.x * blockDim.x + threadIdx.x;
    if (e >= nE) return;
    int d = g_is64 ? (int)((const long long*)ei)[nE + e]
                   : ((const int*)ei)[nE + e];
    atomicAdd(&g_cnt[d], 1);
}

__global__ void k_scan1() {
    __shared__ int sh[256];
    int t = threadIdx.x, b = blockIdx.x;
    int i = b * 256 + t;
    int v = (i < NN) ? g_cnt[i] : 0;
    sh[t] = v;
    __syncthreads();
    #pragma unroll
    for (int off = 1; off < 256; off <<= 1) {
        int u = (t >= off) ? sh[t - off] : 0;
        __syncthreads();
        sh[t] += u;
        __syncthreads();
    }
    if (i < NN) g_exc[i] = sh[t] - v;
    if (t == 255) g_bsum[b] = sh[t];
}

__global__ void k_scan23() {
    __shared__ int red[8];
    __shared__ int boff;
    int b = blockIdx.x, t = threadIdx.x;
    int v = 0;
    if (t < b) v = g_bsum[t];
    if (t + 256 < b) v += g_bsum[t + 256];
    #pragma unroll
    for (int o = 16; o; o >>= 1) v += __shfl_xor_sync(0xffffffffu, v, o);
    if ((t & 31) == 0) red[t >> 5] = v;
    __syncthreads();
    if (t == 0) {
        int s = 0;
        #pragma unroll
        for (int j = 0; j < 8; ++j) s += red[j];
        boff = s;
    }
    __syncthreads();
    int i = b * 256 + t;
    if (i < NN) {
        int row = g_exc[i] + boff;
        g_rowptr[i] = row;
        g_cur[i] = row;
        g_invdeg[i] = 1.0f / fmaxf((float)g_cnt[i], 1.0f);
    }
}

__global__ void k_fill(const void* __restrict__ ei, int nE) {
    int e = blockIdx.x * blockDim.x + threadIdx.x;
    if (e >= nE) return;
    int s, d;
    if (g_is64) {
        const long long* p = (const long long*)ei;
        s = (int)p[e]; d = (int)p[nE + e];
    } else {
        const int* p = (const int*)ei;
        s = p[e]; d = p[nE + e];
    }
    int pos = atomicAdd(&g_cur[d], 1);
    g_srcs[pos] = s;
}

// ---------------------------------------------------------------------------
// GEMM1 (r12 measured core): double-buffered pipeline, 128x128 tile,
// 256 threads, 8x8 microtile, K-chunk 16. Epilogue now stores fp16.
// ---------------------------------------------------------------------------
__global__ void __launch_bounds__(256, 2)
k_gemm1(const float* __restrict__ x,
        const float* __restrict__ Wl,
        const float* __restrict__ Wr,
        const float* __restrict__ b) {
    __shared__ float As[2][16][130];
    __shared__ u64   Bs2[2][16][128];

    int tid = threadIdx.x;
    int tx = tid & 15;
    int ty = tid >> 4;
    int m0 = blockIdx.x * 128;

    int am  = tid >> 2;
    int akk = (tid & 3) * 4;
    int amg0 = min(m0 + am, NN - 1);
    int amg1 = min(m0 + am + 64, NN - 1);
    int bk = tid >> 4;
    int bn = (tid & 15) * 8;

    u64 acc[4][8] = {};
    float4 pa0, pa1, pb0, pb1;

    pa0 = __ldg((const float4*)(x + (size_t)amg0 * DD + akk));
    pa1 = __ldg((const float4*)(x + (size_t)amg1 * DD + akk));
    {
        const float* W = (bn < 64) ? (Wl + (size_t)bk * 64 + bn)
                                   : (Wr + (size_t)bk * 64 + (bn - 64));
        pb0 = __ldg((const float4*)(W));
        pb1 = __ldg((const float4*)(W + 4));
    }
    As[0][akk + 0][am] = pa0.x; As[0][akk + 1][am] = pa0.y;
    As[0][akk + 2][am] = pa0.z; As[0][akk + 3][am] = pa0.w;
    As[0][akk + 0][am + 64] = pa1.x; As[0][akk + 1][am + 64] = pa1.y;
    As[0][akk + 2][am + 64] = pa1.z; As[0][akk + 3][am + 64] = pa1.w;
    Bs2[0][bk][bn + 0] = pack2(pb0.x, pb0.x);
    Bs2[0][bk][bn + 1] = pack2(pb0.y, pb0.y);
    Bs2[0][bk][bn + 2] = pack2(pb0.z, pb0.z);
    Bs2[0][bk][bn + 3] = pack2(pb0.w, pb0.w);
    Bs2[0][bk][bn + 4] = pack2(pb1.x, pb1.x);
    Bs2[0][bk][bn + 5] = pack2(pb1.y, pb1.y);
    Bs2[0][bk][bn + 6] = pack2(pb1.z, pb1.z);
    Bs2[0][bk][bn + 7] = pack2(pb1.w, pb1.w);
    __syncthreads();

    #pragma unroll 1
    for (int c = 0; c < 8; ++c) {
        int p = c & 1;
        const float (*Ab)[130] = As[p];
        const u64   (*Bb)[128] = Bs2[p];

        if (c < 7) {
            int kb = (c + 1) * 16;
            pa0 = __ldg((const float4*)(x + (size_t)amg0 * DD + kb + akk));
            pa1 = __ldg((const float4*)(x + (size_t)amg1 * DD + kb + akk));
            const float* W = (bn < 64) ? (Wl + (size_t)(kb + bk) * 64 + bn)
                                       : (Wr + (size_t)(kb + bk) * 64 + (bn - 64));
            pb0 = __ldg((const float4*)(W));
            pb1 = __ldg((const float4*)(W + 4));
        }

        #pragma unroll
        for (int k = 0; k < 8; ++k) {
            u64 Ap[4];
            #pragma unroll
            for (int i = 0; i < 4; ++i)
                Ap[i] = *(const u64*)&Ab[k][ty * 8 + 2 * i];
            #pragma unroll
            for (int j = 0; j < 8; ++j) {
                u64 Bv = Bb[k][j * 16 + tx];
                fma2(acc[0][j], Ap[0], Bv);
                fma2(acc[1][j], Ap[1], Bv);
                fma2(acc[2][j], Ap[2], Bv);
                fma2(acc[3][j], Ap[3], Bv);
            }
        }

        if (c < 7) {
            int q = p ^ 1;
            As[q][akk + 0][am] = pa0.x; As[q][akk + 1][am] = pa0.y;
            As[q][akk + 2][am] = pa0.z; As[q][akk + 3][am] = pa0.w;
            As[q][akk + 0][am + 64] = pa1.x; As[q][akk + 1][am + 64] = pa1.y;
            As[q][akk + 2][am + 64] = pa1.z; As[q][akk + 3][am + 64] = pa1.w;
            Bs2[q][bk][bn + 0] = pack2(pb0.x, pb0.x);
            Bs2[q][bk][bn + 1] = pack2(pb0.y, pb0.y);
            Bs2[q][bk][bn + 2] = pack2(pb0.z, pb0.z);
            Bs2[q][bk][bn + 3] = pack2(pb0.w, pb0.w);
            Bs2[q][bk][bn + 4] = pack2(pb1.x, pb1.x);
            Bs2[q][bk][bn + 5] = pack2(pb1.y, pb1.y);
            Bs2[q][bk][bn + 6] = pack2(pb1.z, pb1.z);
            Bs2[q][bk][bn + 7] = pack2(pb1.w, pb1.w);
        }

        #pragma unroll
        for (int k = 8; k < 16; ++k) {
            u64 Ap[4];
            #pragma unroll
            for (int i = 0; i < 4; ++i)
                Ap[i] = *(const u64*)&Ab[k][ty * 8 + 2 * i];
            #pragma unroll
            for (int j = 0; j < 8; ++j) {
                u64 Bv = Bb[k][j * 16 + tx];
                fma2(acc[0][j], Ap[0], Bv);
                fma2(acc[1][j], Ap[1], Bv);
                fma2(acc[2][j], Ap[2], Bv);
                fma2(acc[3][j], Ap[3], Bv);
            }
        }
        __syncthreads();
    }

    // epilogue: col<64 -> g_y1h ; col>=64 -> g_selfh (+b1), fp16 stores
    #pragma unroll
    for (int j = 0; j < 8; ++j) {
        int col = j * 16 + tx;
        bool isSelf = (col >= 64);
        int nc = isSelf ? (col - 64) : col;
        float bb = isSelf ? b[nc] : 0.f;
        __half* dst = isSelf ? g_selfh : g_y1h;
        #pragma unroll
        for (int i = 0; i < 4; ++i) {
            float v0, v1;
            unpack2(acc[i][j], v0, v1);
            int r0 = m0 + ty * 8 + 2 * i;
            if (r0 < NN)     dst[(size_t)r0 * HH + nc]       = __float2half_rn(v0 + bb);
            if (r0 + 1 < NN) dst[(size_t)(r0 + 1) * HH + nc] = __float2half_rn(v1 + bb);
        }
    }
}

// ---------------------------------------------------------------------------
// agg1 + ReLU: h[n] = relu( invdeg * sum_{s} y1[s] + self[n] )
// warp per node, lane -> half2 (128B/row gather), fp32 accumulation.
// ---------------------------------------------------------------------------
__global__ void k_agg1(void) {
    int w = (blockIdx.x * blockDim.x + threadIdx.x) >> 5;
    int lane = threadIdx.x & 31;
    if (w >= NN) return;
    int beg = g_rowptr[w], n = g_cnt[w];
    const __half2* yb = (const __half2*)g_y1h;   // 32 half2 per row
    float2 a0 = make_float2(0.f, 0.f), a1 = make_float2(0.f, 0.f);
    int e = 0;
    for (; e + 1 < n; e += 2) {
        int s0 = g_srcs[beg + e];
        int s1 = g_srcs[beg + e + 1];
        float2 v0 = __half22float2(__ldg(yb + (size_t)s0 * 32 + lane));
        float2 v1 = __half22float2(__ldg(yb + (size_t)s1 * 32 + lane));
        a0.x += v0.x; a0.y += v0.y;
        a1.x += v1.x; a1.y += v1.y;
    }
    if (e < n) {
        int s0 = g_srcs[beg + e];
        float2 v0 = __half22float2(__ldg(yb + (size_t)s0 * 32 + lane));
        a0.x += v0.x; a0.y += v0.y;
    }
    float sc = g_invdeg[w];
    float2 s = __half22float2(((const __half2*)g_selfh)[(size_t)w * 32 + lane]);
    float2 o;
    o.x = fmaxf((a0.x + a1.x) * sc + s.x, 0.f);
    o.y = fmaxf((a0.y + a1.y) * sc + s.y, 0.f);
    ((__half2*)g_hh)[(size_t)w * 32 + lane] = __float22half2_rn(o);
}

// ---------------------------------------------------------------------------
// agg2: g_agg2[n] = invdeg * sum_{s} h[s]   (half2 gather, fp32 out)
// ---------------------------------------------------------------------------
__global__ void k_agg2(void) {
    int w = (blockIdx.x * blockDim.x + threadIdx.x) >> 5;
    int lane = threadIdx.x & 31;
    if (w >= NN) return;
    int beg = g_rowptr[w], n = g_cnt[w];
    const __half2* hb = (const __half2*)g_hh;
    float2 a0 = make_float2(0.f, 0.f), a1 = make_float2(0.f, 0.f);
    int e = 0;
    for (; e + 1 < n; e += 2) {
        int s0 = g_srcs[beg + e];
        int s1 = g_srcs[beg + e + 1];
        float2 v0 = __half22float2(__ldg(hb + (size_t)s0 * 32 + lane));
        float2 v1 = __half22float2(__ldg(hb + (size_t)s1 * 32 + lane));
        a0.x += v0.x; a0.y += v0.y;
        a1.x += v1.x; a1.y += v1.y;
    }
    if (e < n) {
        int s0 = g_srcs[beg + e];
        float2 v0 = __half22float2(__ldg(hb + (size_t)s0 * 32 + lane));
        a0.x += v0.x; a0.y += v0.y;
    }
    float sc = g_invdeg[w];
    float2 o;
    o.x = (a0.x + a1.x) * sc;
    o.y = (a0.y + a1.y) * sc;
    ((float2*)g_agg2)[(size_t)w * 32 + lane] = o;
}

// ---------------------------------------------------------------------------
// GEMM2 + fused log_softmax, persistent grid-stride, packed f32x2.
// agg features: fp32, layout (lane, lane+32). h features: fp16 half2,
// layout (2*lane, 2*lane+1). Shfl indices resolved at compile time.
// ---------------------------------------------------------------------------
__global__ void __launch_bounds__(256)
k_gemm2(const float* __restrict__ Wl,
        const float* __restrict__ Wr,
        const float* __restrict__ b,
        float* __restrict__ out) {
    __shared__ float2 sW[64 * 40];
    __shared__ float sb[40];
    int tid = threadIdx.x;
    for (int i = tid; i < 64 * 40; i += blockDim.x)
        sW[i] = make_float2(Wl[i], Wr[i]);
    if (tid < 40) sb[tid] = b[tid];
    __syncthreads();

    int lane = tid & 31;
    bool lo8 = (lane < 8);
    int gwarp = (blockIdx.x * blockDim.x + tid) >> 5;
    int nwarps = (gridDim.x * blockDim.x) >> 5;

    for (int w = gwarp; w < NN; w += nwarps) {
        const float* ag = g_agg2 + (size_t)w * HH;
        float a0 = ag[lane], a1 = ag[lane + 32];
        float2 hf = __half22float2(((const __half2*)g_hh)[(size_t)w * 32 + lane]);
        float hlo = hf.x, hhi = hf.y;   // features 2*lane, 2*lane+1

        u64 acc0 = 0, acc1 = 0;
        #pragma unroll
        for (int f = 0; f < 64; ++f) {
            float av = __shfl_sync(0xffffffffu, (f < 32) ? a0 : a1, f & 31);
            float hv = __shfl_sync(0xffffffffu, (f & 1) ? hhi : hlo, f >> 1);
            u64 p = pack2(av, hv);
            fma2(acc0, p, *(const u64*)&sW[f * 40 + lane]);
            if (lo8) fma2(acc1, p, *(const u64*)&sW[f * 40 + 32 + lane]);
        }

        float u0, v0, u1, v1;
        unpack2(acc0, u0, v0);
        unpack2(acc1, u1, v1);
        float z0 = u0 + v0 + sb[lane];
        float z1 = lo8 ? (u1 + v1 + sb[32 + lane]) : -INFINITY;

        float m = fmaxf(z0, z1);
        #pragma unroll
        for (int o = 16; o; o >>= 1) m = fmaxf(m, __shfl_xor_sync(0xffffffffu, m, o));
        float e = expf(z0 - m) + (lo8 ? expf(z1 - m) : 0.f);
        #pragma unroll
        for (int o = 16; o; o >>= 1) e += __shfl_xor_sync(0xffffffffu, e, o);
        float lse = logf(e) + m;

        out[(size_t)w * CC + lane] = z0 - lse;
        if (lo8) out[(size_t)w * CC + 32 + lane] = z1 - lse;
    }
}

// ---------------------------------------------------------------------------
extern "C" void kernel_launch(void* const* d_in, const int* in_sizes, int n_in,
                              void* d_out, int out_size) {
    const float* x   = (const float*)d_in[0];
    const void*  ei  = d_in[1];
    const float* W1l = (const float*)d_in[2];
    const float* W1r = (const float*)d_in[3];
    const float* b1  = (const float*)d_in[4];
    const float* W2l = (const float*)d_in[5];
    const float* W2r = (const float*)d_in[6];
    const float* b2  = (const float*)d_in[7];
    float* out = (float*)d_out;

    int nE = in_sizes[1] / 2;
    int eBlocks = (nE + 255) / 256;
    int nWarpBlocks = (NN * 32 + 255) / 256;

    k_detzero<<<(NN + 255) / 256, 256>>>(ei);            // 1
    k_hist<<<eBlocks, 256>>>(ei, nE);                    // 2
    k_scan1<<<NB, 256>>>();                              // 3
    k_gemm1<<<(NN + 127) / 128, 256>>>(x, W1l, W1r, b1); // 4 <- ncu window
    k_scan23<<<NB, 256>>>();                             // 5
    k_fill<<<eBlocks, 256>>>(ei, nE);                    // 6
    k_agg1<<<nWarpBlocks, 256>>>();                      // 7
    k_agg2<<<nWarpBlocks, 256>>>();                      // 8
    k_gemm2<<<1184, 256>>>(W2l, W2r, b2, out);           // 9 persistent
}